// round 1
// baseline (speedup 1.0000x reference)
#include <cuda_runtime.h>
#include <math.h>

#define LSEQ 2048
#define NZ 4            // (branch, batch) pairs: z = br*2 + b

// ---------------- scratch (device globals; no runtime allocation) ----------
__device__ float g_xz  [NZ * 512 * LSEQ];   // in_proj output [z][512][L]
__device__ float g_xc  [NZ * 256 * LSEQ];   // silu(conv(x))  [z][256][L]  (= u)
__device__ float g_xdbl[NZ * 288 * LSEQ];   // x_proj output  [z][288][L]  (dt|B|C rows)
__device__ float g_dlt [NZ * 256 * LSEQ];   // delta          [z][256][L]
__device__ float g_y   [NZ * 512 * LSEQ];   // concat(y, z)   [z][512][L]
__device__ float g_A   [2 * 256 * 128];     // A1, A2
__device__ float g_maxes[8];                // [2+br]=maxB, [4+br]=maxC

// ---------------- helpers ---------------------------------------------------
__device__ __forceinline__ float spf(float v, float thr) {
    float a = fabsf(v) - thr;
    a = a > 0.f ? a : 0.f;
    return (v > 0.f) ? a : (v < 0.f ? -a : 0.f);
}
__device__ __forceinline__ float siluf(float v) {
    return v / (1.f + expf(-v));
}
__device__ __forceinline__ float softplusf(float v) {
    return (v > 20.f) ? v : log1pf(expf(v));
}
__device__ __forceinline__ float negInf() { return __int_as_float(0xff800000); }

__device__ float blockReduceMax(float v) {
    __shared__ float sh[32];
    __syncthreads();
    #pragma unroll
    for (int o = 16; o; o >>= 1) v = fmaxf(v, __shfl_xor_sync(0xffffffffu, v, o));
    if ((threadIdx.x & 31) == 0) sh[threadIdx.x >> 5] = v;
    __syncthreads();
    float r = negInf();
    if (threadIdx.x < (blockDim.x >> 5)) r = sh[threadIdx.x];
    if ((threadIdx.x >> 5) == 0) {
        #pragma unroll
        for (int o = 16; o; o >>= 1) r = fmaxf(r, __shfl_xor_sync(0xffffffffu, r, o));
        if (threadIdx.x == 0) sh[0] = r;
    }
    __syncthreads();
    return sh[0];
}

__device__ __forceinline__ void atomicMaxFloat(float* addr, float val) {
    if (val >= 0.f) atomicMax((int*)addr, __float_as_int(val));
    else            atomicMin((unsigned int*)addr, __float_as_uint(val));
}

// ---------------- A preparation (single block) ------------------------------
__global__ void prep_A(const float* __restrict__ Alog, const float* __restrict__ eps) {
    const int N = 256 * 128;
    float e = 1.f + eps[0];
    float m = negInf();
    for (int i = threadIdx.x; i < N; i += blockDim.x)
        m = fmaxf(m, -e * expf(Alog[i]));
    float thr1 = 0.1f * blockReduceMax(m);
    float m2 = negInf();
    for (int i = threadIdx.x; i < N; i += blockDim.x) {
        float a1 = spf(-e * expf(Alog[i]), thr1);
        g_A[i] = a1;
        m2 = fmaxf(m2, a1);
    }
    float thr2 = 0.1f * blockReduceMax(m2);
    for (int i = threadIdx.x; i < N; i += blockDim.x)
        g_A[N + i] = spf(g_A[i], thr2);
    if (threadIdx.x == 0) {
        g_maxes[2] = g_maxes[3] = g_maxes[4] = g_maxes[5] = negInf();
    }
}

// ---------------- generic tiled fp32 GEMM -----------------------------------
// C[z][m][l] (or transposed store C[z][l][m]) = sum_k W_z[m][k] * X_z[k][l]
// W row-major (K contiguous); X row-major (N contiguous, row stride = N).
template <bool TRANS>
__global__ void gemm_k(const float* __restrict__ Wa, const float* __restrict__ Wb,
                       const float* __restrict__ X, long xsb, long xsbr,
                       float* __restrict__ C, long csz, int ldC,
                       int M, int N, int K) {
    int z = blockIdx.z, br = z >> 1, b = z & 1;
    const float* W  = br ? Wb : Wa;
    const float* Xp = X + (long)b * xsb + (long)br * xsbr;
    float*       Cp = C + (long)z * csz;

    __shared__ float As[16][68];
    __shared__ float Bs[16][64];

    int tid = threadIdx.x;
    int tx = tid & 15, ty = tid >> 4;
    int m0 = blockIdx.y * 64, n0 = blockIdx.x * 64;

    int arow = tid >> 2, ac4 = (tid & 3) << 2;
    int brow = tid >> 4, bc4 = (tid & 15) << 2;

    float acc[4][4];
    #pragma unroll
    for (int i = 0; i < 4; i++)
        #pragma unroll
        for (int j = 0; j < 4; j++) acc[i][j] = 0.f;

    for (int k0 = 0; k0 < K; k0 += 16) {
        float4 av = make_float4(0.f, 0.f, 0.f, 0.f);
        int gm = m0 + arow;
        if (gm < M) av = *(const float4*)&W[(long)gm * K + k0 + ac4];
        float4 bv = *(const float4*)&Xp[(long)(k0 + brow) * N + n0 + bc4];
        As[ac4 + 0][arow] = av.x; As[ac4 + 1][arow] = av.y;
        As[ac4 + 2][arow] = av.z; As[ac4 + 3][arow] = av.w;
        *(float4*)&Bs[brow][bc4] = bv;
        __syncthreads();
        #pragma unroll
        for (int k = 0; k < 16; k++) {
            float a0 = As[k][ty], a1 = As[k][ty + 16], a2 = As[k][ty + 32], a3 = As[k][ty + 48];
            float4 b4 = *(float4*)&Bs[k][tx << 2];
            acc[0][0] = fmaf(a0, b4.x, acc[0][0]); acc[0][1] = fmaf(a0, b4.y, acc[0][1]);
            acc[0][2] = fmaf(a0, b4.z, acc[0][2]); acc[0][3] = fmaf(a0, b4.w, acc[0][3]);
            acc[1][0] = fmaf(a1, b4.x, acc[1][0]); acc[1][1] = fmaf(a1, b4.y, acc[1][1]);
            acc[1][2] = fmaf(a1, b4.z, acc[1][2]); acc[1][3] = fmaf(a1, b4.w, acc[1][3]);
            acc[2][0] = fmaf(a2, b4.x, acc[2][0]); acc[2][1] = fmaf(a2, b4.y, acc[2][1]);
            acc[2][2] = fmaf(a2, b4.z, acc[2][2]); acc[2][3] = fmaf(a2, b4.w, acc[2][3]);
            acc[3][0] = fmaf(a3, b4.x, acc[3][0]); acc[3][1] = fmaf(a3, b4.y, acc[3][1]);
            acc[3][2] = fmaf(a3, b4.z, acc[3][2]); acc[3][3] = fmaf(a3, b4.w, acc[3][3]);
        }
        __syncthreads();
    }

    if constexpr (!TRANS) {
        #pragma unroll
        for (int i = 0; i < 4; i++) {
            int gm = m0 + ty + 16 * i;
            if (gm < M)
                *(float4*)&Cp[(long)gm * ldC + n0 + (tx << 2)] =
                    make_float4(acc[i][0], acc[i][1], acc[i][2], acc[i][3]);
        }
    } else {
        __shared__ float Ts[64][68];
        #pragma unroll
        for (int i = 0; i < 4; i++)
            #pragma unroll
            for (int j = 0; j < 4; j++)
                Ts[(tx << 2) + j][ty + 16 * i] = acc[i][j];
        __syncthreads();
        #pragma unroll
        for (int r = 0; r < 4; r++) {
            int ll = (tid >> 4) + 16 * r;
            int mm = (tid & 15) << 2;
            float4 v = *(float4*)&Ts[ll][mm];
            *(float4*)&Cp[(long)(n0 + ll) * ldC + m0 + mm] = v;
        }
    }
}

// ---------------- depthwise conv (k=4, pad L1/R2) + silu --------------------
__global__ void conv_silu(const float* __restrict__ cxw0, const float* __restrict__ czw0,
                          const float* __restrict__ cxw1, const float* __restrict__ czw1) {
    long idx = (long)blockIdx.x * blockDim.x + threadIdx.x;  // 4*256*L total
    int l = idx & (LSEQ - 1);
    int d = (int)((idx >> 11) & 255);
    int z = (int)(idx >> 19);
    int br = z >> 1;
    const float* wx = (br ? cxw1 : cxw0) + d * 4;
    const float* wz = (br ? czw1 : czw0) + d * 4;
    const float* xrow = g_xz + ((long)z * 512 + d) * LSEQ;
    const float* zrow = g_xz + ((long)z * 512 + 256 + d) * LSEQ;
    float ax = 0.f, az = 0.f;
    #pragma unroll
    for (int j = 0; j < 4; j++) {
        int ll = l + j - 1;
        if (ll >= 0 && ll < LSEQ) {
            ax = fmaf(wx[j], xrow[ll], ax);
            az = fmaf(wz[j], zrow[ll], az);
        }
    }
    g_xc[((long)z * 256 + d) * LSEQ + l] = siluf(ax);
    g_y [((long)z * 512 + 256 + d) * LSEQ + l] = siluf(az);
}

// ---------------- softplus(dt + bias) ---------------------------------------
__global__ void softplus_k(const float* __restrict__ b0, const float* __restrict__ b1) {
    long idx = (long)blockIdx.x * blockDim.x + threadIdx.x;  // 4*256*L total
    int d = (int)((idx >> 11) & 255);
    int z = (int)(idx >> 19);
    float bias = ((z >> 1) ? b1 : b0)[d];
    g_dlt[idx] = softplusf(g_dlt[idx] + bias);
}

// ---------------- global max over Bc / Cc slices -----------------------------
__global__ void maxBC_k() {
    int which = blockIdx.y;   // 0 = B rows [32,160), 1 = C rows [160,288)
    int br    = blockIdx.z;
    int poff  = 32 + which * 128;
    float m = negInf();
    const long per = 128L * LSEQ;
    const long total = 2 * per;
    for (long i = (long)blockIdx.x * blockDim.x + threadIdx.x; i < total;
         i += (long)gridDim.x * blockDim.x) {
        int b = (int)(i / per);
        long rem = i - (long)b * per;
        m = fmaxf(m, g_xdbl[(long)((br * 2 + b) * 288 + poff) * LSEQ + rem]);
    }
    m = blockReduceMax(m);
    if (threadIdx.x == 0) atomicMaxFloat(&g_maxes[2 + which * 2 + br], m);
}

// ---------------- selective scan ---------------------------------------------
// grid (32 dblocks, b=2, br=2); block 256 = 8 warps; warp -> one d; lane -> 4 n.
__global__ void scan_k(const float* __restrict__ Dv) {
    __shared__ float sB[32][128];
    __shared__ float sC[32][128];
    __shared__ float sdl[8][32];
    __shared__ float sul[8][32];
    __shared__ float sy [8][32];

    int tid = threadIdx.x;
    int w = tid >> 5, lane = tid & 31;
    int b = blockIdx.y, br = blockIdx.z, z = br * 2 + b;
    int d = blockIdx.x * 8 + w;

    float thrB = 0.1f * g_maxes[2 + br];
    float thrC = 0.1f * g_maxes[4 + br];
    float4 av = *(const float4*)&g_A[((long)br * 256 + d) * 128 + (lane << 2)];
    float Dd = Dv[d];
    float h0 = 0.f, h1 = 0.f, h2 = 0.f, h3 = 0.f;

    const float* Bbase = g_xdbl + ((long)z * 288 + 32)  * LSEQ;
    const float* Cbase = g_xdbl + ((long)z * 288 + 160) * LSEQ;
    const float* dbase = g_dlt  + ((long)z * 256 + d)   * LSEQ;
    const float* ubase = g_xc   + ((long)z * 256 + d)   * LSEQ;
    float*       ybase = g_y    + ((long)z * 512 + blockIdx.x * 8) * LSEQ;

    for (int t0 = 0; t0 < LSEQ; t0 += 32) {
        __syncthreads();
        // stage B/C tile (transposed) with sparse threshold applied
        #pragma unroll
        for (int cc = 0; cc < 4; cc++) {
            int linear = cc * 256 + tid;         // 0..1023
            int n  = linear & 127;
            int g4 = (linear >> 7) << 2;         // 0,4,...,28
            float4 v = *(const float4*)&Bbase[(long)n * LSEQ + t0 + g4];
            sB[g4 + 0][n] = spf(v.x, thrB); sB[g4 + 1][n] = spf(v.y, thrB);
            sB[g4 + 2][n] = spf(v.z, thrB); sB[g4 + 3][n] = spf(v.w, thrB);
            float4 c = *(const float4*)&Cbase[(long)n * LSEQ + t0 + g4];
            sC[g4 + 0][n] = spf(c.x, thrC); sC[g4 + 1][n] = spf(c.y, thrC);
            sC[g4 + 2][n] = spf(c.z, thrC); sC[g4 + 3][n] = spf(c.w, thrC);
        }
        sdl[w][lane] = dbase[t0 + lane];
        sul[w][lane] = ubase[t0 + lane];
        __syncthreads();

        #pragma unroll 4
        for (int tt = 0; tt < 32; tt++) {
            float delta = sdl[w][tt];
            float u = sul[w][tt];
            float du = delta * u;
            float4 Bv = *(float4*)&sB[tt][lane << 2];
            float4 Cv = *(float4*)&sC[tt][lane << 2];
            h0 = fmaf(__expf(delta * av.x), h0, du * Bv.x);
            h1 = fmaf(__expf(delta * av.y), h1, du * Bv.y);
            h2 = fmaf(__expf(delta * av.z), h2, du * Bv.z);
            h3 = fmaf(__expf(delta * av.w), h3, du * Bv.w);
            float p = fmaf(h0, Cv.x, fmaf(h1, Cv.y, fmaf(h2, Cv.z, h3 * Cv.w)));
            p += __shfl_xor_sync(0xffffffffu, p, 16);
            p += __shfl_xor_sync(0xffffffffu, p, 8);
            p += __shfl_xor_sync(0xffffffffu, p, 4);
            p += __shfl_xor_sync(0xffffffffu, p, 2);
            p += __shfl_xor_sync(0xffffffffu, p, 1);
            if (lane == 0) sy[w][tt] = p + u * Dd;
        }
        __syncthreads();
        {   // coalesced y store (folds +u*D already)
            int ww = tid >> 5, tt = tid & 31;
            ybase[(long)ww * LSEQ + t0 + tt] = sy[ww][tt];
        }
    }
}

// ---------------- launch ------------------------------------------------------
extern "C" void kernel_launch(void* const* d_in, const int* in_sizes, int n_in,
                              void* d_out, int out_size) {
    const float* inp  = (const float*)d_in[0];
    const float* inw  = (const float*)d_in[1];
    const float* cxw  = (const float*)d_in[2];
    const float* czw  = (const float*)d_in[3];
    const float* xpw  = (const float*)d_in[4];
    const float* dtw  = (const float*)d_in[5];
    const float* dtb  = (const float*)d_in[6];
    const float* ow   = (const float*)d_in[7];
    const float* inw2 = (const float*)d_in[8];
    const float* cxw2 = (const float*)d_in[9];
    const float* czw2 = (const float*)d_in[10];
    const float* xpw2 = (const float*)d_in[11];
    const float* dtw2 = (const float*)d_in[12];
    const float* dtb2 = (const float*)d_in[13];
    const float* ow2  = (const float*)d_in[14];
    const float* Alog = (const float*)d_in[15];
    const float* Dv   = (const float*)d_in[16];
    const float* eps  = (const float*)d_in[17];
    float* out = (float*)d_out;

    float *p_xz, *p_xc, *p_xdbl, *p_dlt, *p_y;
    cudaGetSymbolAddress((void**)&p_xz,   g_xz);
    cudaGetSymbolAddress((void**)&p_xc,   g_xc);
    cudaGetSymbolAddress((void**)&p_xdbl, g_xdbl);
    cudaGetSymbolAddress((void**)&p_dlt,  g_dlt);
    cudaGetSymbolAddress((void**)&p_y,    g_y);

    const long L = LSEQ;

    // A1/A2 + init maxes
    prep_A<<<1, 1024>>>(Alog, eps);

    // in_proj: xz[z][512][L]
    gemm_k<false><<<dim3(32, 8, 4), 256>>>(inw, inw2, inp, 1024 * L, 512 * L,
                                           p_xz, 512 * L, LSEQ, 512, LSEQ, 512);
    // depthwise conv + silu (x -> g_xc, z -> g_y[256:512])
    conv_silu<<<8192, 256>>>(cxw, czw, cxw2, czw2);

    // x_proj: xdbl[z][288][L]
    gemm_k<false><<<dim3(32, 5, 4), 256>>>(xpw, xpw2, p_xc, 256 * L, 512 * L,
                                           p_xdbl, 288 * L, LSEQ, 288, LSEQ, 256);
    // dt_proj: dlt[z][256][L]  (raw, bias+softplus next)
    gemm_k<false><<<dim3(32, 4, 4), 256>>>(dtw, dtw2, p_xdbl, 288 * L, 576 * L,
                                           p_dlt, 256 * L, LSEQ, 256, LSEQ, 32);
    softplus_k<<<8192, 256>>>(dtb, dtb2);

    // global maxes of Bc / Cc per branch
    maxBC_k<<<dim3(64, 2, 2), 256>>>();

    // selective scan -> g_y[0:256] (includes +u*D)
    scan_k<<<dim3(32, 2, 2), 256>>>(Dv);

    // out_proj with transposed store -> out[z][L][512]
    gemm_k<true><<<dim3(32, 8, 4), 256>>>(ow, ow2, p_y, 512 * L, 1024 * L,
                                          out, L * 512, 512, 512, LSEQ, 512);
}

// round 2
// speedup vs baseline: 1.1076x; 1.1076x over previous
#include <cuda_runtime.h>
#include <math.h>

#define LSEQ 2048
#define NZ 4            // (branch, batch) pairs: z = br*2 + b

// ---------------- scratch (device globals; no runtime allocation) ----------
__device__ float g_xz  [NZ * 512 * LSEQ];   // in_proj output [z][512][L]
__device__ float g_xc  [NZ * 256 * LSEQ];   // silu(conv(x))  [z][256][L]  (= u)
__device__ float g_xdbl[NZ * 288 * LSEQ];   // x_proj output  [z][288][L]  (dt|B|C rows)
__device__ float g_dlt [NZ * 256 * LSEQ];   // delta          [z][256][L]
__device__ float g_y   [NZ * 512 * LSEQ];   // concat(y, z)   [z][512][L]
__device__ float g_A   [2 * 256 * 128];     // A1, A2
__device__ float g_maxes[8];                // [2+br]=maxB, [4+br]=maxC

// ---------------- helpers ---------------------------------------------------
__device__ __forceinline__ float spf(float v, float thr) {
    float a = fabsf(v) - thr;
    a = a > 0.f ? a : 0.f;
    return (v > 0.f) ? a : (v < 0.f ? -a : 0.f);
}
__device__ __forceinline__ float siluf(float v) {
    return v / (1.f + expf(-v));
}
__device__ __forceinline__ float softplusf(float v) {
    return (v > 20.f) ? v : log1pf(expf(v));
}
__device__ __forceinline__ float ex2f(float x) {
    float r; asm("ex2.approx.f32 %0, %1;" : "=f"(r) : "f"(x)); return r;
}
__device__ __forceinline__ float negInf() { return __int_as_float(0xff800000); }

__device__ float blockReduceMax(float v) {
    __shared__ float sh[32];
    __syncthreads();
    #pragma unroll
    for (int o = 16; o; o >>= 1) v = fmaxf(v, __shfl_xor_sync(0xffffffffu, v, o));
    if ((threadIdx.x & 31) == 0) sh[threadIdx.x >> 5] = v;
    __syncthreads();
    float r = negInf();
    if (threadIdx.x < (blockDim.x >> 5)) r = sh[threadIdx.x];
    if ((threadIdx.x >> 5) == 0) {
        #pragma unroll
        for (int o = 16; o; o >>= 1) r = fmaxf(r, __shfl_xor_sync(0xffffffffu, r, o));
        if (threadIdx.x == 0) sh[0] = r;
    }
    __syncthreads();
    return sh[0];
}

__device__ __forceinline__ void atomicMaxFloat(float* addr, float val) {
    if (val >= 0.f) atomicMax((int*)addr, __float_as_int(val));
    else            atomicMin((unsigned int*)addr, __float_as_uint(val));
}

// ---------------- A preparation (single block) ------------------------------
__global__ void prep_A(const float* __restrict__ Alog, const float* __restrict__ eps) {
    const int N = 256 * 128;
    float e = 1.f + eps[0];
    float m = negInf();
    for (int i = threadIdx.x; i < N; i += blockDim.x)
        m = fmaxf(m, -e * expf(Alog[i]));
    float thr1 = 0.1f * blockReduceMax(m);
    float m2 = negInf();
    for (int i = threadIdx.x; i < N; i += blockDim.x) {
        float a1 = spf(-e * expf(Alog[i]), thr1);
        g_A[i] = a1;
        m2 = fmaxf(m2, a1);
    }
    float thr2 = 0.1f * blockReduceMax(m2);
    for (int i = threadIdx.x; i < N; i += blockDim.x)
        g_A[N + i] = spf(g_A[i], thr2);
    if (threadIdx.x == 0) {
        g_maxes[2] = g_maxes[3] = g_maxes[4] = g_maxes[5] = negInf();
    }
}

// ---------------- 128x128x8 fp32 GEMM, 8x8 per thread ------------------------
// C[z][m][l] = sum_k W_z[m][k] * X_z[k][l]
// EPI 0: plain store   EPI 1: transposed store C[z][l][m]
// EPI 2: softplus(v + bias[m]) then plain store
template <int EPI>
__global__ void __launch_bounds__(256) gemm128(
    const float* __restrict__ Wa, const float* __restrict__ Wb,
    const float* __restrict__ X, long xsb, long xsbr,
    float* __restrict__ C, long csz, int ldC,
    int M, int N, int K,
    const float* __restrict__ biasA, const float* __restrict__ biasB)
{
    int z = blockIdx.z, br = z >> 1, b = z & 1;
    const float* W  = br ? Wb : Wa;
    const float* Xp = X + (long)b * xsb + (long)br * xsbr;
    float*       Cp = C + (long)z * csz;

    __shared__ float As[8][128];
    __shared__ float Bs[8][128];

    int tid = threadIdx.x;
    int tx = tid & 15, ty = tid >> 4;
    int m0 = blockIdx.y * 128, n0 = blockIdx.x * 128;

    int arow = tid >> 1;           // 0..127
    int ak   = (tid & 1) * 4;      // 0 or 4
    int brow = tid >> 5;           // 0..7
    int bn   = (tid & 31) * 4;     // 0..124

    const float* Aptr = W + (long)(m0 + arow) * K + ak;
    bool arow_ok = (m0 + arow) < M;
    const float* Bptr = Xp + (long)brow * N + n0 + bn;

    float acc[8][8];
    #pragma unroll
    for (int i = 0; i < 8; i++)
        #pragma unroll
        for (int j = 0; j < 8; j++) acc[i][j] = 0.f;

    float4 pa = arow_ok ? *(const float4*)Aptr : make_float4(0.f, 0.f, 0.f, 0.f);
    float4 pb = *(const float4*)Bptr;

    for (int k0 = 0; k0 < K; k0 += 8) {
        As[ak + 0][arow] = pa.x; As[ak + 1][arow] = pa.y;
        As[ak + 2][arow] = pa.z; As[ak + 3][arow] = pa.w;
        *(float4*)&Bs[brow][bn] = pb;
        __syncthreads();
        if (k0 + 8 < K) {
            pa = arow_ok ? *(const float4*)(Aptr + k0 + 8) : make_float4(0.f, 0.f, 0.f, 0.f);
            pb = *(const float4*)(Bptr + (long)(k0 + 8) * N);
        }
        #pragma unroll
        for (int kk = 0; kk < 8; kk++) {
            float4 a0 = *(float4*)&As[kk][ty * 4];
            float4 a1 = *(float4*)&As[kk][64 + ty * 4];
            float4 b0 = *(float4*)&Bs[kk][tx * 4];
            float4 b1 = *(float4*)&Bs[kk][64 + tx * 4];
            float am[8] = {a0.x, a0.y, a0.z, a0.w, a1.x, a1.y, a1.z, a1.w};
            float bv[8] = {b0.x, b0.y, b0.z, b0.w, b1.x, b1.y, b1.z, b1.w};
            #pragma unroll
            for (int i = 0; i < 8; i++)
                #pragma unroll
                for (int j = 0; j < 8; j++)
                    acc[i][j] = fmaf(am[i], bv[j], acc[i][j]);
        }
        __syncthreads();
    }

    if constexpr (EPI == 1) {
        // transposed store: Cp[n * ldC + m]
        #pragma unroll
        for (int j = 0; j < 8; j++) {
            int nj = n0 + (j < 4 ? tx * 4 + j : 64 + tx * 4 + (j - 4));
            float4 v0 = make_float4(acc[0][j], acc[1][j], acc[2][j], acc[3][j]);
            float4 v1 = make_float4(acc[4][j], acc[5][j], acc[6][j], acc[7][j]);
            *(float4*)&Cp[(long)nj * ldC + m0 + ty * 4]      = v0;
            *(float4*)&Cp[(long)nj * ldC + m0 + 64 + ty * 4] = v1;
        }
    } else {
        const float* bp = (EPI == 2) ? (br ? biasB : biasA) : nullptr;
        #pragma unroll
        for (int i = 0; i < 8; i++) {
            int mi = m0 + (i < 4 ? ty * 4 + i : 64 + ty * 4 + (i - 4));
            if (mi < M) {
                float r[8];
                #pragma unroll
                for (int j = 0; j < 8; j++) r[j] = acc[i][j];
                if (EPI == 2) {
                    float bias = bp[mi];
                    #pragma unroll
                    for (int j = 0; j < 8; j++) r[j] = softplusf(r[j] + bias);
                }
                *(float4*)&Cp[(long)mi * ldC + n0 + tx * 4] =
                    make_float4(r[0], r[1], r[2], r[3]);
                *(float4*)&Cp[(long)mi * ldC + n0 + 64 + tx * 4] =
                    make_float4(r[4], r[5], r[6], r[7]);
            }
        }
    }
}

// ---------------- depthwise conv (k=4, pad L1/R2) + silu --------------------
__global__ void conv_silu(const float* __restrict__ cxw0, const float* __restrict__ czw0,
                          const float* __restrict__ cxw1, const float* __restrict__ czw1) {
    long idx = (long)blockIdx.x * blockDim.x + threadIdx.x;  // 4*256*L total
    int l = idx & (LSEQ - 1);
    int d = (int)((idx >> 11) & 255);
    int z = (int)(idx >> 19);
    int br = z >> 1;
    const float* wx = (br ? cxw1 : cxw0) + d * 4;
    const float* wz = (br ? czw1 : czw0) + d * 4;
    const float* xrow = g_xz + ((long)z * 512 + d) * LSEQ;
    const float* zrow = g_xz + ((long)z * 512 + 256 + d) * LSEQ;
    float ax = 0.f, az = 0.f;
    #pragma unroll
    for (int j = 0; j < 4; j++) {
        int ll = l + j - 1;
        if (ll >= 0 && ll < LSEQ) {
            ax = fmaf(wx[j], xrow[ll], ax);
            az = fmaf(wz[j], zrow[ll], az);
        }
    }
    g_xc[((long)z * 256 + d) * LSEQ + l] = siluf(ax);
    g_y [((long)z * 512 + 256 + d) * LSEQ + l] = siluf(az);
}

// ---------------- global max over Bc / Cc slices -----------------------------
__global__ void maxBC_k() {
    int which = blockIdx.y;   // 0 = B rows [32,160), 1 = C rows [160,288)
    int br    = blockIdx.z;
    int poff  = 32 + which * 128;
    float m = negInf();
    const long per = 128L * LSEQ;
    const long total = 2 * per;
    for (long i = (long)blockIdx.x * blockDim.x + threadIdx.x; i < total;
         i += (long)gridDim.x * blockDim.x) {
        int b = (int)(i / per);
        long rem = i - (long)b * per;
        m = fmaxf(m, g_xdbl[(long)((br * 2 + b) * 288 + poff) * LSEQ + rem]);
    }
    m = blockReduceMax(m);
    if (threadIdx.x == 0) atomicMaxFloat(&g_maxes[2 + which * 2 + br], m);
}

// ---------------- selective scan ---------------------------------------------
// grid (32 dblocks, b=2, br=2); block 256 = 8 warps; warp -> one d;
// lane owns n in {lane, lane+32, lane+64, lane+96}.
// B/C tiles staged coalesced into [n][t] layout, stride 33 (conflict-free).
#define SCTS 33
__global__ void __launch_bounds__(256) scan_k(const float* __restrict__ Dv) {
    __shared__ float sB[128 * SCTS];
    __shared__ float sC[128 * SCTS];
    __shared__ float sdl[8][32];
    __shared__ float sdu[8][32];
    __shared__ float sul[8][32];
    __shared__ float sy [8][32];

    int tid = threadIdx.x;
    int w = tid >> 5, lane = tid & 31;
    int b = blockIdx.y, br = blockIdx.z, z = br * 2 + b;
    int d = blockIdx.x * 8 + w;

    float thrB = 0.1f * g_maxes[2 + br];
    float thrC = 0.1f * g_maxes[4 + br];
    const float LOG2E = 1.4426950408889634f;
    const float* Arow = g_A + ((long)br * 256 + d) * 128;
    float a0 = Arow[lane]      * LOG2E;
    float a1 = Arow[lane + 32] * LOG2E;
    float a2 = Arow[lane + 64] * LOG2E;
    float a3 = Arow[lane + 96] * LOG2E;
    float Dd = Dv[d];
    float h0 = 0.f, h1 = 0.f, h2 = 0.f, h3 = 0.f;

    const float* Bbase = g_xdbl + ((long)z * 288 + 32)  * LSEQ;
    const float* Cbase = g_xdbl + ((long)z * 288 + 160) * LSEQ;
    const float* dbase = g_dlt  + ((long)z * 256 + d)   * LSEQ;
    const float* ubase = g_xc   + ((long)z * 256 + d)   * LSEQ;
    float*       ybase = g_y    + ((long)z * 512 + blockIdx.x * 8) * LSEQ;

    for (int t0 = 0; t0 < LSEQ; t0 += 32) {
        __syncthreads();
        // coalesced staging: [128 n] x [32 t] tiles, transposed to [n][t]
        #pragma unroll
        for (int cc = 0; cc < 4; cc++) {
            int lin = cc * 256 + tid;       // 0..1023
            int row = lin >> 3;             // n
            int tq  = (lin & 7) << 2;       // t quad
            float4 v = *(const float4*)&Bbase[(long)row * LSEQ + t0 + tq];
            sB[row * SCTS + tq + 0] = spf(v.x, thrB);
            sB[row * SCTS + tq + 1] = spf(v.y, thrB);
            sB[row * SCTS + tq + 2] = spf(v.z, thrB);
            sB[row * SCTS + tq + 3] = spf(v.w, thrB);
            float4 c = *(const float4*)&Cbase[(long)row * LSEQ + t0 + tq];
            sC[row * SCTS + tq + 0] = spf(c.x, thrC);
            sC[row * SCTS + tq + 1] = spf(c.y, thrC);
            sC[row * SCTS + tq + 2] = spf(c.z, thrC);
            sC[row * SCTS + tq + 3] = spf(c.w, thrC);
        }
        {
            float dl = dbase[t0 + lane];
            float uu = ubase[t0 + lane];
            sdl[w][lane] = dl;
            sdu[w][lane] = dl * uu;
            sul[w][lane] = uu;
        }
        __syncthreads();

        #pragma unroll 4
        for (int tt = 0; tt < 32; tt++) {
            float delta = sdl[w][tt];
            float du    = sdu[w][tt];
            float b0 = sB[(lane      ) * SCTS + tt];
            float b1 = sB[(lane + 32 ) * SCTS + tt];
            float b2 = sB[(lane + 64 ) * SCTS + tt];
            float b3 = sB[(lane + 96 ) * SCTS + tt];
            float c0 = sC[(lane      ) * SCTS + tt];
            float c1 = sC[(lane + 32 ) * SCTS + tt];
            float c2 = sC[(lane + 64 ) * SCTS + tt];
            float c3 = sC[(lane + 96 ) * SCTS + tt];
            h0 = fmaf(ex2f(delta * a0), h0, du * b0);
            h1 = fmaf(ex2f(delta * a1), h1, du * b1);
            h2 = fmaf(ex2f(delta * a2), h2, du * b2);
            h3 = fmaf(ex2f(delta * a3), h3, du * b3);
            float p = fmaf(h0, c0, fmaf(h1, c1, fmaf(h2, c2, h3 * c3)));
            p += __shfl_xor_sync(0xffffffffu, p, 16);
            p += __shfl_xor_sync(0xffffffffu, p, 8);
            p += __shfl_xor_sync(0xffffffffu, p, 4);
            p += __shfl_xor_sync(0xffffffffu, p, 2);
            p += __shfl_xor_sync(0xffffffffu, p, 1);
            if (lane == 0) sy[w][tt] = fmaf(sul[w][tt], Dd, p);
        }
        __syncthreads();
        {   // coalesced y store
            int ww = tid >> 5, tt = tid & 31;
            ybase[(long)ww * LSEQ + t0 + tt] = sy[ww][tt];
        }
    }
}

// ---------------- launch ------------------------------------------------------
extern "C" void kernel_launch(void* const* d_in, const int* in_sizes, int n_in,
                              void* d_out, int out_size) {
    const float* inp  = (const float*)d_in[0];
    const float* inw  = (const float*)d_in[1];
    const float* cxw  = (const float*)d_in[2];
    const float* czw  = (const float*)d_in[3];
    const float* xpw  = (const float*)d_in[4];
    const float* dtw  = (const float*)d_in[5];
    const float* dtb  = (const float*)d_in[6];
    const float* ow   = (const float*)d_in[7];
    const float* inw2 = (const float*)d_in[8];
    const float* cxw2 = (const float*)d_in[9];
    const float* czw2 = (const float*)d_in[10];
    const float* xpw2 = (const float*)d_in[11];
    const float* dtw2 = (const float*)d_in[12];
    const float* dtb2 = (const float*)d_in[13];
    const float* ow2  = (const float*)d_in[14];
    const float* Alog = (const float*)d_in[15];
    const float* Dv   = (const float*)d_in[16];
    const float* eps  = (const float*)d_in[17];
    float* out = (float*)d_out;

    float *p_xz, *p_xc, *p_xdbl, *p_dlt, *p_y;
    cudaGetSymbolAddress((void**)&p_xz,   g_xz);
    cudaGetSymbolAddress((void**)&p_xc,   g_xc);
    cudaGetSymbolAddress((void**)&p_xdbl, g_xdbl);
    cudaGetSymbolAddress((void**)&p_dlt,  g_dlt);
    cudaGetSymbolAddress((void**)&p_y,    g_y);

    const long L = LSEQ;

    // A1/A2 + init maxes
    prep_A<<<1, 1024>>>(Alog, eps);

    // in_proj: xz[z][512][L]
    gemm128<0><<<dim3(16, 4, 4), 256>>>(inw, inw2, inp, 1024 * L, 512 * L,
                                        p_xz, 512 * L, LSEQ, 512, LSEQ, 512,
                                        nullptr, nullptr);
    // depthwise conv + silu (x -> g_xc, z -> g_y[256:512])
    conv_silu<<<8192, 256>>>(cxw, czw, cxw2, czw2);

    // x_proj: xdbl[z][288][L]
    gemm128<0><<<dim3(16, 3, 4), 256>>>(xpw, xpw2, p_xc, 256 * L, 512 * L,
                                        p_xdbl, 288 * L, LSEQ, 288, LSEQ, 256,
                                        nullptr, nullptr);
    // global maxes of Bc / Cc per branch
    maxBC_k<<<dim3(64, 2, 2), 256>>>();

    // dt_proj fused with bias + softplus: dlt[z][256][L]
    gemm128<2><<<dim3(16, 2, 4), 256>>>(dtw, dtw2, p_xdbl, 288 * L, 576 * L,
                                        p_dlt, 256 * L, LSEQ, 256, LSEQ, 32,
                                        dtb, dtb2);

    // selective scan -> g_y[0:256] (includes +u*D)
    scan_k<<<dim3(32, 2, 2), 256>>>(Dv);

    // out_proj with transposed store -> out[z][L][512]
    gemm128<1><<<dim3(16, 4, 4), 256>>>(ow, ow2, p_y, 512 * L, 1024 * L,
                                        out, L * 512, 512, 512, LSEQ, 512,
                                        nullptr, nullptr);
}

// round 3
// speedup vs baseline: 1.2925x; 1.1669x over previous
#include <cuda_runtime.h>
#include <math.h>

#define LSEQ 2048
#define NZ 4            // (branch, batch) pairs: z = br*2 + b

// ---------------- scratch (device globals; no runtime allocation) ----------
__device__ float g_xz  [NZ * 512 * LSEQ];   // in_proj output [z][512][L]
__device__ float g_xc  [NZ * 256 * LSEQ];   // silu(conv(x))  [z][256][L]  (= u)
__device__ float g_xdbl[NZ * 288 * LSEQ];   // x_proj output  [z][288][L]  (dt|B|C rows)
__device__ float g_y   [NZ * 512 * LSEQ];   // concat(y, z)   [z][512][L]
__device__ float g_A   [2 * 256 * 128];     // A1, A2
__device__ float g_maxes[8];                // [2+br]=maxB, [4+br]=maxC
__device__ float g_D32 [2 * 256];           // per (br,d): A[n+32]-A[n] if affine
__device__ int   g_lin [2 * 256];           // per (br,d): affine-in-n flag

// ---------------- helpers ---------------------------------------------------
__device__ __forceinline__ float spf(float v, float thr) {
    float a = fabsf(v) - thr;
    a = a > 0.f ? a : 0.f;
    return (v > 0.f) ? a : (v < 0.f ? -a : 0.f);
}
__device__ __forceinline__ float siluf(float v) {
    return v / (1.f + expf(-v));
}
__device__ __forceinline__ float softplusf(float v) {
    return (v > 20.f) ? v : log1pf(expf(v));
}
__device__ __forceinline__ float ex2f(float x) {
    float r; asm("ex2.approx.f32 %0, %1;" : "=f"(r) : "f"(x)); return r;
}
__device__ __forceinline__ float negInf() { return __int_as_float(0xff800000); }

__device__ float blockReduceMax(float v) {
    __shared__ float sh[32];
    __syncthreads();
    #pragma unroll
    for (int o = 16; o; o >>= 1) v = fmaxf(v, __shfl_xor_sync(0xffffffffu, v, o));
    if ((threadIdx.x & 31) == 0) sh[threadIdx.x >> 5] = v;
    __syncthreads();
    float r = negInf();
    if (threadIdx.x < (blockDim.x >> 5)) r = sh[threadIdx.x];
    if ((threadIdx.x >> 5) == 0) {
        #pragma unroll
        for (int o = 16; o; o >>= 1) r = fmaxf(r, __shfl_xor_sync(0xffffffffu, r, o));
        if (threadIdx.x == 0) sh[0] = r;
    }
    __syncthreads();
    return sh[0];
}

// sign-safe float atomic max via CAS
__device__ __forceinline__ void atomicMaxFloatCAS(float* addr, float val) {
    int* ai = (int*)addr;
    int old = *ai;
    while (__int_as_float(old) < val) {
        int assumed = old;
        old = atomicCAS(ai, assumed, __float_as_int(val));
        if (old == assumed) break;
    }
}

// ---------------- A preparation (single block) ------------------------------
__global__ void prep_A(const float* __restrict__ Alog, const float* __restrict__ eps) {
    const int N = 256 * 128;
    float e = 1.f + eps[0];
    float m = negInf();
    for (int i = threadIdx.x; i < N; i += blockDim.x)
        m = fmaxf(m, -e * expf(Alog[i]));
    float thr1 = 0.1f * blockReduceMax(m);
    float m2 = negInf();
    for (int i = threadIdx.x; i < N; i += blockDim.x) {
        float a1 = spf(-e * expf(Alog[i]), thr1);
        g_A[i] = a1;
        m2 = fmaxf(m2, a1);
    }
    float thr2 = 0.1f * blockReduceMax(m2);
    for (int i = threadIdx.x; i < N; i += blockDim.x)
        g_A[N + i] = spf(g_A[i], thr2);
    __syncthreads();
    // affinity-in-n check per (br,d) row: A[n+32]-A[n] ~= const
    for (int idx = threadIdx.x; idx < 512; idx += blockDim.x) {
        const float* row = g_A + (long)idx * 128;
        float d32 = row[32] - row[0];
        bool ok = true;
        #pragma unroll 4
        for (int n = 0; n < 96; n++)
            ok = ok && (fabsf((row[n + 32] - row[n]) - d32) <= 1e-3f);
        g_D32[idx] = d32;
        g_lin[idx] = ok ? 1 : 0;
    }
    if (threadIdx.x == 0) {
        g_maxes[2] = g_maxes[3] = g_maxes[4] = g_maxes[5] = negInf();
    }
}

// ---------------- 128x128x8 fp32 GEMM, 8x8/thread, smem double-buffered ------
// C[z][m][l] = sum_k W_z[m][k] * X_z[k][l]
// EPI 0: plain store   EPI 1: transposed store C[z][l][m]
// EPI 3: plain store + fused global max of rows [32,160) -> maxB, [160,288) -> maxC
template <int EPI>
__global__ void __launch_bounds__(256) gemm128(
    const float* __restrict__ Wa, const float* __restrict__ Wb,
    const float* __restrict__ X, long xsb, long xsbr,
    float* __restrict__ C, long csz, int ldC,
    int M, int N, int K)
{
    int z = blockIdx.z, br = z >> 1, b = z & 1;
    const float* W  = br ? Wb : Wa;
    const float* Xp = X + (long)b * xsb + (long)br * xsbr;
    float*       Cp = C + (long)z * csz;

    __shared__ float As[2][8][128];
    __shared__ float Bs[2][8][128];

    int tid = threadIdx.x;
    int tx = tid & 15, ty = tid >> 4;
    int m0 = blockIdx.y * 128, n0 = blockIdx.x * 128;

    int arow = tid >> 1;           // 0..127
    int ak   = (tid & 1) * 4;      // 0 or 4
    int brow = tid >> 5;           // 0..7
    int bn   = (tid & 31) * 4;     // 0..124

    const float* Aptr = W + (long)(m0 + arow) * K + ak;
    bool arow_ok = (m0 + arow) < M;
    const float* Bptr = Xp + (long)brow * N + n0 + bn;

    float acc[8][8];
    #pragma unroll
    for (int i = 0; i < 8; i++)
        #pragma unroll
        for (int j = 0; j < 8; j++) acc[i][j] = 0.f;

    float4 pa = arow_ok ? *(const float4*)Aptr : make_float4(0.f, 0.f, 0.f, 0.f);
    float4 pb = *(const float4*)Bptr;
    As[0][ak + 0][arow] = pa.x; As[0][ak + 1][arow] = pa.y;
    As[0][ak + 2][arow] = pa.z; As[0][ak + 3][arow] = pa.w;
    *(float4*)&Bs[0][brow][bn] = pb;
    __syncthreads();

    int s = 0;
    for (int k0 = 0; k0 < K; k0 += 8) {
        bool more = (k0 + 8) < K;
        if (more) {
            pa = arow_ok ? *(const float4*)(Aptr + k0 + 8) : make_float4(0.f, 0.f, 0.f, 0.f);
            pb = *(const float4*)(Bptr + (long)(k0 + 8) * N);
        }
        #pragma unroll
        for (int kk = 0; kk < 8; kk++) {
            float4 a0 = *(float4*)&As[s][kk][ty * 4];
            float4 a1 = *(float4*)&As[s][kk][64 + ty * 4];
            float4 b0 = *(float4*)&Bs[s][kk][tx * 4];
            float4 b1 = *(float4*)&Bs[s][kk][64 + tx * 4];
            float am[8] = {a0.x, a0.y, a0.z, a0.w, a1.x, a1.y, a1.z, a1.w};
            float bv[8] = {b0.x, b0.y, b0.z, b0.w, b1.x, b1.y, b1.z, b1.w};
            #pragma unroll
            for (int i = 0; i < 8; i++)
                #pragma unroll
                for (int j = 0; j < 8; j++)
                    acc[i][j] = fmaf(am[i], bv[j], acc[i][j]);
        }
        if (more) {
            As[s ^ 1][ak + 0][arow] = pa.x; As[s ^ 1][ak + 1][arow] = pa.y;
            As[s ^ 1][ak + 2][arow] = pa.z; As[s ^ 1][ak + 3][arow] = pa.w;
            *(float4*)&Bs[s ^ 1][brow][bn] = pb;
            __syncthreads();
            s ^= 1;
        }
    }

    if constexpr (EPI == 1) {
        // transposed store: Cp[n * ldC + m]
        #pragma unroll
        for (int j = 0; j < 8; j++) {
            int nj = n0 + (j < 4 ? tx * 4 + j : 64 + tx * 4 + (j - 4));
            float4 v0 = make_float4(acc[0][j], acc[1][j], acc[2][j], acc[3][j]);
            float4 v1 = make_float4(acc[4][j], acc[5][j], acc[6][j], acc[7][j]);
            *(float4*)&Cp[(long)nj * ldC + m0 + ty * 4]      = v0;
            *(float4*)&Cp[(long)nj * ldC + m0 + 64 + ty * 4] = v1;
        }
    } else {
        float mB = negInf(), mC = negInf();
        #pragma unroll
        for (int i = 0; i < 8; i++) {
            int mi = m0 + (i < 4 ? ty * 4 + i : 64 + ty * 4 + (i - 4));
            if (mi < M) {
                *(float4*)&Cp[(long)mi * ldC + n0 + tx * 4] =
                    make_float4(acc[i][0], acc[i][1], acc[i][2], acc[i][3]);
                *(float4*)&Cp[(long)mi * ldC + n0 + 64 + tx * 4] =
                    make_float4(acc[i][4], acc[i][5], acc[i][6], acc[i][7]);
                if (EPI == 3) {
                    float mx = acc[i][0];
                    #pragma unroll
                    for (int j = 1; j < 8; j++) mx = fmaxf(mx, acc[i][j]);
                    if (mi >= 32 && mi < 160)  mB = fmaxf(mB, mx);
                    if (mi >= 160)             mC = fmaxf(mC, mx);
                }
            }
        }
        if (EPI == 3) {
            #pragma unroll
            for (int o = 16; o; o >>= 1) {
                mB = fmaxf(mB, __shfl_xor_sync(0xffffffffu, mB, o));
                mC = fmaxf(mC, __shfl_xor_sync(0xffffffffu, mC, o));
            }
            if ((tid & 31) == 0) {
                if (mB > negInf()) atomicMaxFloatCAS(&g_maxes[2 + br], mB);
                if (mC > negInf()) atomicMaxFloatCAS(&g_maxes[4 + br], mC);
            }
        }
    }
}

// ---------------- depthwise conv (k=4, pad L1/R2) + silu --------------------
__global__ void conv_silu(const float* __restrict__ cxw0, const float* __restrict__ czw0,
                          const float* __restrict__ cxw1, const float* __restrict__ czw1) {
    long idx = (long)blockIdx.x * blockDim.x + threadIdx.x;  // 4*256*L total
    int l = idx & (LSEQ - 1);
    int d = (int)((idx >> 11) & 255);
    int z = (int)(idx >> 19);
    int br = z >> 1;
    const float* wx = (br ? cxw1 : cxw0) + d * 4;
    const float* wz = (br ? czw1 : czw0) + d * 4;
    const float* xrow = g_xz + ((long)z * 512 + d) * LSEQ;
    const float* zrow = g_xz + ((long)z * 512 + 256 + d) * LSEQ;
    float ax = 0.f, az = 0.f;
    #pragma unroll
    for (int j = 0; j < 4; j++) {
        int ll = l + j - 1;
        if (ll >= 0 && ll < LSEQ) {
            ax = fmaf(wx[j], xrow[ll], ax);
            az = fmaf(wz[j], zrow[ll], az);
        }
    }
    g_xc[((long)z * 256 + d) * LSEQ + l] = siluf(ax);
    g_y [((long)z * 512 + 256 + d) * LSEQ + l] = siluf(az);
}

// ---------------- selective scan (dt_proj + softplus fused) ------------------
// grid (32 dblocks, b=2, br=2); block 256 = 8 warps; warp w -> d = bx*8+w;
// lane owns n in {lane, lane+32, lane+64, lane+96}.
#define SCTS 33
__global__ void __launch_bounds__(256) scan_k(
    const float* __restrict__ Dv,
    const float* __restrict__ dtwA, const float* __restrict__ dtwB,
    const float* __restrict__ dtbA, const float* __restrict__ dtbB)
{
    __shared__ float sB[128 * SCTS];
    __shared__ float sC[128 * SCTS];
    __shared__ float sdt[32][SCTS];   // xdbl dt-rows tile [32 k][32 t]
    __shared__ float swt[8][32];      // dt weights per d
    __shared__ float sdl[8][32];
    __shared__ float sdu[8][32];

    int tid = threadIdx.x;
    int w = tid >> 5, lane = tid & 31;
    int b = blockIdx.y, br = blockIdx.z, z = br * 2 + b;
    int d = blockIdx.x * 8 + w;

    float thrB = 0.1f * g_maxes[2 + br];
    float thrC = 0.1f * g_maxes[4 + br];
    const float LOG2E = 1.4426950408889634f;
    const float* Arow = g_A + ((long)br * 256 + d) * 128;
    float a0 = Arow[lane]      * LOG2E;
    float a1 = Arow[lane + 32] * LOG2E;
    float a2 = Arow[lane + 64] * LOG2E;
    float a3 = Arow[lane + 96] * LOG2E;
    int   lin  = g_lin[br * 256 + d];
    float r32p = g_D32[br * 256 + d] * LOG2E;
    float Dd = Dv[d];
    float bias = (br ? dtbB : dtbA)[d];
    float h0 = 0.f, h1 = 0.f, h2 = 0.f, h3 = 0.f;

    // dt weights: swt[d_local][j]
    swt[w][lane] = ((br ? dtwB : dtwA))[d * 32 + lane];

    const float* Bbase  = g_xdbl + ((long)z * 288 + 32)  * LSEQ;
    const float* Cbase  = g_xdbl + ((long)z * 288 + 160) * LSEQ;
    const float* dtbase = g_xdbl + ((long)z * 288)       * LSEQ;
    const float* ubase  = g_xc   + ((long)z * 256 + d)   * LSEQ;
    float*       ybase  = g_y    + ((long)z * 512 + blockIdx.x * 8 + w) * LSEQ;

    for (int t0 = 0; t0 < LSEQ; t0 += 32) {
        __syncthreads();
        // stage B/C (coalesced, transpose to [n][t]) with sparse threshold
        #pragma unroll
        for (int cc = 0; cc < 4; cc++) {
            int lin2 = cc * 256 + tid;      // 0..1023
            int row = lin2 >> 3;            // n
            int tq  = (lin2 & 7) << 2;      // t quad
            float4 v = *(const float4*)&Bbase[(long)row * LSEQ + t0 + tq];
            sB[row * SCTS + tq + 0] = spf(v.x, thrB);
            sB[row * SCTS + tq + 1] = spf(v.y, thrB);
            sB[row * SCTS + tq + 2] = spf(v.z, thrB);
            sB[row * SCTS + tq + 3] = spf(v.w, thrB);
            float4 c = *(const float4*)&Cbase[(long)row * LSEQ + t0 + tq];
            sC[row * SCTS + tq + 0] = spf(c.x, thrC);
            sC[row * SCTS + tq + 1] = spf(c.y, thrC);
            sC[row * SCTS + tq + 2] = spf(c.z, thrC);
            sC[row * SCTS + tq + 3] = spf(c.w, thrC);
        }
        {   // stage dt rows tile (32 rows x 32 t)
            int row = tid >> 3;
            int tq  = (tid & 7) << 2;
            float4 v = *(const float4*)&dtbase[(long)row * LSEQ + t0 + tq];
            sdt[row][tq + 0] = v.x; sdt[row][tq + 1] = v.y;
            sdt[row][tq + 2] = v.z; sdt[row][tq + 3] = v.w;
        }
        __syncthreads();
        {   // delta = softplus(dtw[d] . xdbl_dt[:,t] + bias); thread (w,lane) -> (d, t=lane)
            float acc = bias;
            #pragma unroll
            for (int j = 0; j < 32; j++)
                acc = fmaf(swt[w][j], sdt[j][lane], acc);
            float delta = softplusf(acc);
            float uu = ubase[t0 + lane];
            sdl[w][lane] = delta;
            sdu[w][lane] = delta * uu;
            h3 += 0.f;  // keep compiler honest
            // stash u*D for the final add (register, used after butterfly)
        }
        float uD = ubase[t0 + lane] * Dd;
        __syncthreads();

        float p[32];
        #pragma unroll
        for (int tt = 0; tt < 32; tt++) {
            float delta = sdl[w][tt];
            float du    = sdu[w][tt];
            float b0 = sB[(lane      ) * SCTS + tt];
            float b1 = sB[(lane + 32 ) * SCTS + tt];
            float b2 = sB[(lane + 64 ) * SCTS + tt];
            float b3 = sB[(lane + 96 ) * SCTS + tt];
            float c0 = sC[(lane      ) * SCTS + tt];
            float c1 = sC[(lane + 32 ) * SCTS + tt];
            float c2 = sC[(lane + 64 ) * SCTS + tt];
            float c3 = sC[(lane + 96 ) * SCTS + tt];
            float dA0, dA1, dA2, dA3;
            if (lin) {
                dA0 = ex2f(delta * a0);
                float r = ex2f(delta * r32p);
                dA1 = dA0 * r; dA2 = dA1 * r; dA3 = dA2 * r;
            } else {
                dA0 = ex2f(delta * a0); dA1 = ex2f(delta * a1);
                dA2 = ex2f(delta * a2); dA3 = ex2f(delta * a3);
            }
            h0 = fmaf(dA0, h0, du * b0);
            h1 = fmaf(dA1, h1, du * b1);
            h2 = fmaf(dA2, h2, du * b2);
            h3 = fmaf(dA3, h3, du * b3);
            p[tt] = fmaf(h0, c0, fmaf(h1, c1, fmaf(h2, c2, h3 * c3)));
        }

        // butterfly transpose-reduce: lane L ends with sum over lanes of p[L]
        #pragma unroll
        for (int m = 16, len = 16; m >= 1; m >>= 1, len >>= 1) {
            bool hi = (lane & m) != 0;
            #pragma unroll
            for (int i = 0; i < 16; i++) {
                if (i >= len) break;
                float send = hi ? p[i] : p[i + len];
                float recv = __shfl_xor_sync(0xffffffffu, send, m);
                p[i] = (hi ? p[i + len] : p[i]) + recv;
            }
        }
        // lane holds y for t = t0 + lane (per-warp row d): coalesced store
        ybase[t0 + lane] = p[0] + uD;
    }
}

// ---------------- launch ------------------------------------------------------
extern "C" void kernel_launch(void* const* d_in, const int* in_sizes, int n_in,
                              void* d_out, int out_size) {
    const float* inp  = (const float*)d_in[0];
    const float* inw  = (const float*)d_in[1];
    const float* cxw  = (const float*)d_in[2];
    const float* czw  = (const float*)d_in[3];
    const float* xpw  = (const float*)d_in[4];
    const float* dtw  = (const float*)d_in[5];
    const float* dtb  = (const float*)d_in[6];
    const float* ow   = (const float*)d_in[7];
    const float* inw2 = (const float*)d_in[8];
    const float* cxw2 = (const float*)d_in[9];
    const float* czw2 = (const float*)d_in[10];
    const float* xpw2 = (const float*)d_in[11];
    const float* dtw2 = (const float*)d_in[12];
    const float* dtb2 = (const float*)d_in[13];
    const float* ow2  = (const float*)d_in[14];
    const float* Alog = (const float*)d_in[15];
    const float* Dv   = (const float*)d_in[16];
    const float* eps  = (const float*)d_in[17];
    float* out = (float*)d_out;

    float *p_xz, *p_xc, *p_xdbl, *p_y;
    cudaGetSymbolAddress((void**)&p_xz,   g_xz);
    cudaGetSymbolAddress((void**)&p_xc,   g_xc);
    cudaGetSymbolAddress((void**)&p_xdbl, g_xdbl);
    cudaGetSymbolAddress((void**)&p_y,    g_y);

    const long L = LSEQ;

    // A1/A2, affine check, init maxes
    prep_A<<<1, 1024>>>(Alog, eps);

    // in_proj: xz[z][512][L]
    gemm128<0><<<dim3(16, 4, 4), 256>>>(inw, inw2, inp, 1024 * L, 512 * L,
                                        p_xz, 512 * L, LSEQ, 512, LSEQ, 512);
    // depthwise conv + silu (x -> g_xc, z -> g_y[256:512])
    conv_silu<<<8192, 256>>>(cxw, czw, cxw2, czw2);

    // x_proj with fused global-max of B/C rows: xdbl[z][288][L]
    gemm128<3><<<dim3(16, 3, 4), 256>>>(xpw, xpw2, p_xc, 256 * L, 512 * L,
                                        p_xdbl, 288 * L, LSEQ, 288, LSEQ, 256);

    // selective scan (dt_proj + softplus fused) -> g_y[0:256] (includes +u*D)
    scan_k<<<dim3(32, 2, 2), 256>>>(Dv, dtw, dtw2, dtb, dtb2);

    // out_proj with transposed store -> out[z][L][512]
    gemm128<1><<<dim3(16, 4, 4), 256>>>(ow, ow2, p_y, 512 * L, 1024 * L,
                                        out, L * 512, 512, 512, LSEQ, 512);
}